// round 14
// baseline (speedup 1.0000x reference)
#include <cuda_runtime.h>
#include <cuda_bf16.h>
#include <cuda_fp16.h>
#include <math.h>

#define N_NODES 100000
#define N_EDGES 1600000
#define IN_FEATS 256
#define HIDDEN 128
#define NEG_SLOPE 0.2f

// ---------------- scratch (device globals; allocation-free) ----------------
__device__ __half g_h[(size_t)N_NODES * HIDDEN];   // fc output, fp16 (gather-only)
__device__ float g_x2[(size_t)N_NODES * HIDDEN];   // elu(layer1 out) = layer2 input
__device__ float g_el[N_NODES];
__device__ float g_er[N_NODES];
__device__ int   g_deg[N_NODES];
__device__ int   g_inc[N_NODES];
__device__ int   g_bsum[128];
__device__ int   g_off[N_NODES + 1];
__device__ int   g_cur[N_NODES];
__device__ int   g_esrc[N_EDGES];
__device__ unsigned g_mx[4];   // encoded max(el), max(er) per layer
// pre-split weights: packed bf16x2 hi/lo planes
__device__ unsigned g_w1hi[128 * IN_FEATS / 2];
__device__ unsigned g_w1lo[128 * IN_FEATS / 2];
__device__ unsigned g_w2hi[128 * HIDDEN / 2];
__device__ unsigned g_w2lo[128 * HIDDEN / 2];

// ---------------- CSR build ----------------
__global__ void k_count(const int* __restrict__ dst) {
    int i = blockIdx.x * blockDim.x + threadIdx.x;
    if (i < N_EDGES) atomicAdd(&g_deg[dst[i]], 1);
}

__global__ void k_scan1() {
    __shared__ int sm[1024];
    int i = blockIdx.x * 1024 + threadIdx.x;
    int v = (i < N_NODES) ? g_deg[i] : 0;
    sm[threadIdx.x] = v;
    __syncthreads();
    #pragma unroll
    for (int o = 1; o < 1024; o <<= 1) {
        int u = (threadIdx.x >= o) ? sm[threadIdx.x - o] : 0;
        __syncthreads();
        sm[threadIdx.x] += u;
        __syncthreads();
    }
    if (i < N_NODES) g_inc[i] = sm[threadIdx.x];
    if (threadIdx.x == 1023) g_bsum[blockIdx.x] = sm[1023];
}

__global__ void k_scan2(int nb) {
    __shared__ int sm[128];
    int t = threadIdx.x;
    int v = (t < nb) ? g_bsum[t] : 0;
    sm[t] = v;
    __syncthreads();
    #pragma unroll
    for (int o = 1; o < 128; o <<= 1) {
        int u = (t >= o) ? sm[t - o] : 0;
        __syncthreads();
        sm[t] += u;
        __syncthreads();
    }
    if (t < nb) g_bsum[t] = sm[t] - v;  // exclusive
}

__global__ void k_scan3() {
    int i = blockIdx.x * blockDim.x + threadIdx.x;
    if (i < N_NODES) {
        int off = g_inc[i] - g_deg[i] + g_bsum[i >> 10];
        g_off[i] = off;
        g_cur[i] = off;
    }
    if (i == 0) g_off[N_NODES] = N_EDGES;
}

__global__ void k_scatter(const int* __restrict__ src, const int* __restrict__ dst) {
    int i = blockIdx.x * blockDim.x + threadIdx.x;
    if (i < N_EDGES) {
        int p = atomicAdd(&g_cur[dst[i]], 1);
        g_esrc[p] = src[i];
    }
}

// ---------------- fp32 -> bf16 hi/lo helpers ----------------
__device__ __forceinline__ unsigned pack_hi(float a, float b, float& la, float& lb) {
    __nv_bfloat16 ha = __float2bfloat16_rn(a);
    __nv_bfloat16 hb = __float2bfloat16_rn(b);
    la = a - __bfloat162float(ha);
    lb = b - __bfloat162float(hb);
    return ((unsigned)__bfloat16_as_ushort(hb) << 16) | (unsigned)__bfloat16_as_ushort(ha);
}

__device__ __forceinline__ unsigned pack_lo(float la, float lb) {
    return ((unsigned)__bfloat16_as_ushort(__float2bfloat16_rn(lb)) << 16) |
           (unsigned)__bfloat16_as_ushort(__float2bfloat16_rn(la));
}

__global__ void k_splitW(const float* __restrict__ W, unsigned* __restrict__ hi,
                         unsigned* __restrict__ lo, int npairs) {
    int i = blockIdx.x * blockDim.x + threadIdx.x;
    if (i < npairs) {
        float a = W[2 * i], b = W[2 * i + 1];
        float la, lb;
        unsigned h = pack_hi(a, b, la, lb);
        hi[i] = h;
        lo[i] = pack_lo(la, lb);
    }
}

// ---------------- float<->ordered-unsigned for atomicMax ----------------
__device__ __forceinline__ unsigned encf(float f) {
    unsigned u = __float_as_uint(f);
    return (u >> 31) ? ~u : (u | 0x80000000u);
}
__device__ __forceinline__ float decf(unsigned e) {
    return (e >> 31) ? __uint_as_float(e ^ 0x80000000u) : __uint_as_float(~e);
}

// ---------------- bf16x3 tensor-core GEMM + fused el/er + global max ------
// H[M,128] (fp16) = A[M,K] @ W[128,K]^T ; g_el/g_er = C-row dot al/ar (fp32);
// per-layer global max of el/er via atomicMax into g_mx.
// 64x128 tile, 256 threads (8 warps, each 32x32), BK=32, register prefetch,
// double-buffered chunk SMEM, 2 CTAs/SM for 4 warps/SMSP latency hiding.

#define SSTR 18                          // uint32 pairs per row: 16 + 2 pad
#define BUFW ((2 * 64 + 2 * 128) * SSTR) // words per buffer: Ahi,Alo(64r) Bhi,Blo(128r)

__device__ __forceinline__ void mma16816(float* d, const unsigned* a, const unsigned* b) {
    asm volatile(
        "mma.sync.aligned.m16n8k16.row.col.f32.bf16.bf16.f32 "
        "{%0,%1,%2,%3}, {%4,%5,%6,%7}, {%8,%9}, {%0,%1,%2,%3};\n"
        : "+f"(d[0]), "+f"(d[1]), "+f"(d[2]), "+f"(d[3])
        : "r"(a[0]), "r"(a[1]), "r"(a[2]), "r"(a[3]), "r"(b[0]), "r"(b[1]));
}

__global__ __launch_bounds__(256, 2) void k_gemm_bf16x3(
    const float* __restrict__ A,
    const unsigned* __restrict__ Whi, const unsigned* __restrict__ Wlo,
    const float* __restrict__ al, const float* __restrict__ ar,
    __half* __restrict__ H, int M, int K, int layer)
{
    extern __shared__ unsigned dyn[];
    float* sel = (float*)(dyn + 2 * BUFW);   // 64
    float* ser = sel + 64;                    // 64
    float* smax = ser + 64;                   // 4

    const int tid  = threadIdx.x;
    const int lane = tid & 31, wid = tid >> 5;
    const int g = lane >> 2, t = lane & 3;
    const int wm = wid >> 2, wn = wid & 3;    // 2 x 4 warp grid (rows x cols)
    const int row0 = blockIdx.x * 64;
    const int K2 = K >> 1;                    // pairs per W row

    if (tid < 64) { sel[tid] = 0.f; ser[tid] = 0.f; }

    float acc[2][4][4];
    #pragma unroll
    for (int mt = 0; mt < 2; mt++)
        #pragma unroll
        for (int nt = 0; nt < 4; nt++)
            #pragma unroll
            for (int j = 0; j < 4; j++) acc[mt][nt][j] = 0.f;

    // A: 64 rows x 8 float4 per chunk = 512 float4 -> 2 per thread
    int arow[2], aq[2];
    #pragma unroll
    for (int i = 0; i < 2; i++) { int idx = tid + i * 256; arow[i] = idx >> 3; aq[i] = idx & 7; }
    // B: 128 rows x 8 uint2 per plane per chunk = 1024 uint2 -> 4 per thread
    int brow[4], bq[4];
    #pragma unroll
    for (int i = 0; i < 4; i++) { int idx = tid + i * 256; brow[i] = idx >> 3; bq[i] = idx & 7; }

    float4 ra[2];
    uint2 bh[4], bl[4];
    const int NC = K / 32;

    // prologue: load chunk 0 to registers
    #pragma unroll
    for (int i = 0; i < 2; i++) {
        int gr = row0 + arow[i];
        ra[i] = (gr < M) ? *(const float4*)(A + (size_t)gr * K + aq[i] * 4)
                         : make_float4(0.f, 0.f, 0.f, 0.f);
    }
    #pragma unroll
    for (int i = 0; i < 4; i++) {
        int bidx = brow[i] * K2 + bq[i] * 2;
        bh[i] = *(const uint2*)(Whi + bidx);
        bl[i] = *(const uint2*)(Wlo + bidx);
    }

    for (int c = 0; c < NC; c++) {
        unsigned* sAhi = dyn + (c & 1) * BUFW;
        unsigned* sAlo = sAhi + 64 * SSTR;
        unsigned* sBhi = sAlo + 64 * SSTR;
        unsigned* sBlo = sBhi + 128 * SSTR;

        // regs -> smem (A split into bf16 hi/lo; B pre-split)
        #pragma unroll
        for (int i = 0; i < 2; i++) {
            int base = arow[i] * SSTR + aq[i] * 2;
            float l0, l1, l2, l3;
            unsigned h0 = pack_hi(ra[i].x, ra[i].y, l0, l1);
            unsigned h1 = pack_hi(ra[i].z, ra[i].w, l2, l3);
            sAhi[base] = h0; sAhi[base + 1] = h1;
            sAlo[base] = pack_lo(l0, l1); sAlo[base + 1] = pack_lo(l2, l3);
        }
        #pragma unroll
        for (int i = 0; i < 4; i++) {
            int base = brow[i] * SSTR + bq[i] * 2;
            sBhi[base] = bh[i].x; sBhi[base + 1] = bh[i].y;
            sBlo[base] = bl[i].x; sBlo[base + 1] = bl[i].y;
        }
        __syncthreads();   // single barrier per chunk (double-buffered)

        // prefetch next chunk while MMAs run
        if (c + 1 < NC) {
            int k0 = (c + 1) * 32;
            #pragma unroll
            for (int i = 0; i < 2; i++) {
                int gr = row0 + arow[i];
                ra[i] = (gr < M) ? *(const float4*)(A + (size_t)gr * K + k0 + aq[i] * 4)
                                 : make_float4(0.f, 0.f, 0.f, 0.f);
            }
            #pragma unroll
            for (int i = 0; i < 4; i++) {
                int bidx = brow[i] * K2 + (k0 >> 1) + bq[i] * 2;
                bh[i] = *(const uint2*)(Whi + bidx);
                bl[i] = *(const uint2*)(Wlo + bidx);
            }
        }

        #pragma unroll
        for (int ks = 0; ks < 2; ks++) {
            const int pb = ks * 8;
            unsigned fahi[2][4], falo[2][4], fbhi[4][2], fblo[4][2];
            #pragma unroll
            for (int mt = 0; mt < 2; mt++) {
                int r0 = (wm * 32 + mt * 16 + g) * SSTR + pb + t;
                int r1 = r0 + 8 * SSTR;
                fahi[mt][0] = sAhi[r0];     fahi[mt][1] = sAhi[r1];
                fahi[mt][2] = sAhi[r0 + 4]; fahi[mt][3] = sAhi[r1 + 4];
                falo[mt][0] = sAlo[r0];     falo[mt][1] = sAlo[r1];
                falo[mt][2] = sAlo[r0 + 4]; falo[mt][3] = sAlo[r1 + 4];
            }
            #pragma unroll
            for (int nt = 0; nt < 4; nt++) {
                int rn = (wn * 32 + nt * 8 + g) * SSTR + pb + t;
                fbhi[nt][0] = sBhi[rn]; fbhi[nt][1] = sBhi[rn + 4];
                fblo[nt][0] = sBlo[rn]; fblo[nt][1] = sBlo[rn + 4];
            }
            #pragma unroll
            for (int mt = 0; mt < 2; mt++)
                #pragma unroll
                for (int nt = 0; nt < 4; nt++) {
                    mma16816(acc[mt][nt], fahi[mt], fbhi[nt]);
                    mma16816(acc[mt][nt], fahi[mt], fblo[nt]);
                    mma16816(acc[mt][nt], falo[mt], fbhi[nt]);
                }
        }
    }
    __syncthreads();

    // epilogue: store H (fp16), and fused el/er row dots (fp32)
    float alv[8], arv[8];
    #pragma unroll
    for (int nt = 0; nt < 4; nt++) {
        int cix = wn * 32 + nt * 8 + t * 2;
        alv[2 * nt] = al[cix];     alv[2 * nt + 1] = al[cix + 1];
        arv[2 * nt] = ar[cix];     arv[2 * nt + 1] = ar[cix + 1];
    }

    #pragma unroll
    for (int mt = 0; mt < 2; mt++) {
        float eA = 0.f, rA = 0.f, eB = 0.f, rB = 0.f;
        #pragma unroll
        for (int nt = 0; nt < 4; nt++) {
            int r = row0 + wm * 32 + mt * 16 + g;
            int col = wn * 32 + nt * 8 + t * 2;
            if (r < M)
                *(__half2*)(H + (size_t)r * 128 + col) =
                    __floats2half2_rn(acc[mt][nt][0], acc[mt][nt][1]);
            if (r + 8 < M)
                *(__half2*)(H + (size_t)(r + 8) * 128 + col) =
                    __floats2half2_rn(acc[mt][nt][2], acc[mt][nt][3]);
            eA += acc[mt][nt][0] * alv[2 * nt] + acc[mt][nt][1] * alv[2 * nt + 1];
            rA += acc[mt][nt][0] * arv[2 * nt] + acc[mt][nt][1] * arv[2 * nt + 1];
            eB += acc[mt][nt][2] * alv[2 * nt] + acc[mt][nt][3] * alv[2 * nt + 1];
            rB += acc[mt][nt][2] * arv[2 * nt] + acc[mt][nt][3] * arv[2 * nt + 1];
        }
        #pragma unroll
        for (int o = 1; o <= 2; o <<= 1) {
            eA += __shfl_xor_sync(0xffffffffu, eA, o);
            rA += __shfl_xor_sync(0xffffffffu, rA, o);
            eB += __shfl_xor_sync(0xffffffffu, eB, o);
            rB += __shfl_xor_sync(0xffffffffu, rB, o);
        }
        if (t == 0) {
            int lr0 = wm * 32 + mt * 16 + g;
            atomicAdd(&sel[lr0], eA);     atomicAdd(&ser[lr0], rA);
            atomicAdd(&sel[lr0 + 8], eB); atomicAdd(&ser[lr0 + 8], rB);
        }
    }
    __syncthreads();

    // write el/er and fold block max into g_mx[2*layer..] (tid<64 = warps 0,1)
    float mel = -3e38f, mer = -3e38f;
    if (tid < 64) {
        bool valid = (row0 + tid) < M;
        float el = sel[tid], er = ser[tid];
        if (valid) {
            g_el[row0 + tid] = el;
            g_er[row0 + tid] = er;
            mel = el; mer = er;
        }
        #pragma unroll
        for (int o = 16; o; o >>= 1) {
            mel = fmaxf(mel, __shfl_xor_sync(0xffffffffu, mel, o));
            mer = fmaxf(mer, __shfl_xor_sync(0xffffffffu, mer, o));
        }
        if (lane == 0) { smax[wid] = mel; smax[2 + wid] = mer; }
    }
    __syncthreads();
    if (tid == 0) {
        float a = fmaxf(smax[0], smax[1]);
        float b = fmaxf(smax[2], smax[3]);
        atomicMax(&g_mx[2 * layer], encf(a));
        atomicMax(&g_mx[2 * layer + 1], encf(b));
    }
}

// ---------------- single-pass segment softmax + aggregation (fp16 gathers) ----
__global__ void k_agg(const __half* __restrict__ Hm,
                      const float* __restrict__ bias,
                      float4* __restrict__ out4, int do_elu, int layer)
{
    int warp = (blockIdx.x * blockDim.x + threadIdx.x) >> 5;
    int lane = threadIdx.x & 31;
    if (warp >= N_NODES) return;
    int d = warp;
    int s = g_off[d], e = g_off[d + 1];
    float4 bv = ((const float4*)bias)[lane];
    float4 v;

    if (s == e) {
        v = bv;
    } else {
        float me = decf(g_mx[2 * layer]) + decf(g_mx[2 * layer + 1]);
        float m = (me > 0.f) ? me : NEG_SLOPE * me;
        float er_d = g_er[d];
        float4 acc = make_float4(0.f, 0.f, 0.f, 0.f);
        float sumw = 0.f;
        int i = s;
        for (; i + 3 < e; i += 4) {
            int sn0 = g_esrc[i],     sn1 = g_esrc[i + 1];
            int sn2 = g_esrc[i + 2], sn3 = g_esrc[i + 3];
            float2 r0 = *(const float2*)(Hm + (size_t)sn0 * 128 + lane * 4);
            float2 r1 = *(const float2*)(Hm + (size_t)sn1 * 128 + lane * 4);
            float2 r2 = *(const float2*)(Hm + (size_t)sn2 * 128 + lane * 4);
            float2 r3 = *(const float2*)(Hm + (size_t)sn3 * 128 + lane * 4);
            float x0 = g_el[sn0] + er_d, x1 = g_el[sn1] + er_d;
            float x2v = g_el[sn2] + er_d, x3 = g_el[sn3] + er_d;
            float w0 = __expf(((x0 > 0.f) ? x0 : NEG_SLOPE * x0) - m);
            float w1 = __expf(((x1 > 0.f) ? x1 : NEG_SLOPE * x1) - m);
            float w2 = __expf(((x2v > 0.f) ? x2v : NEG_SLOPE * x2v) - m);
            float w3 = __expf(((x3 > 0.f) ? x3 : NEG_SLOPE * x3) - m);
            sumw += (w0 + w1) + (w2 + w3);
            float2 a0 = __half22float2(*(__half2*)&r0.x), b0 = __half22float2(*(__half2*)&r0.y);
            float2 a1 = __half22float2(*(__half2*)&r1.x), b1 = __half22float2(*(__half2*)&r1.y);
            float2 a2 = __half22float2(*(__half2*)&r2.x), b2 = __half22float2(*(__half2*)&r2.y);
            float2 a3 = __half22float2(*(__half2*)&r3.x), b3 = __half22float2(*(__half2*)&r3.y);
            acc.x += w0 * a0.x + w1 * a1.x + w2 * a2.x + w3 * a3.x;
            acc.y += w0 * a0.y + w1 * a1.y + w2 * a2.y + w3 * a3.y;
            acc.z += w0 * b0.x + w1 * b1.x + w2 * b2.x + w3 * b3.x;
            acc.w += w0 * b0.y + w1 * b1.y + w2 * b2.y + w3 * b3.y;
        }
        for (; i < e; i++) {
            int sn = g_esrc[i];
            float2 r0 = *(const float2*)(Hm + (size_t)sn * 128 + lane * 4);
            float x = g_el[sn] + er_d;
            float w = __expf(((x > 0.f) ? x : NEG_SLOPE * x) - m);
            sumw += w;
            float2 a0 = __half22float2(*(__half2*)&r0.x), b0 = __half22float2(*(__half2*)&r0.y);
            acc.x += w * a0.x; acc.y += w * a0.y;
            acc.z += w * b0.x; acc.w += w * b0.y;
        }
        float inv = 1.f / sumw;
        v = make_float4(acc.x * inv + bv.x, acc.y * inv + bv.y,
                        acc.z * inv + bv.z, acc.w * inv + bv.w);
    }

    if (do_elu) {
        v.x = (v.x > 0.f) ? v.x : (__expf(v.x) - 1.f);
        v.y = (v.y > 0.f) ? v.y : (__expf(v.y) - 1.f);
        v.z = (v.z > 0.f) ? v.z : (__expf(v.z) - 1.f);
        v.w = (v.w > 0.f) ? v.w : (__expf(v.w) - 1.f);
    }
    out4[(size_t)d * 32 + lane] = v;
}

// ---------------- launch ----------------
extern "C" void kernel_launch(void* const* d_in, const int* in_sizes, int n_in,
                              void* d_out, int out_size)
{
    const float* feats = (const float*)d_in[0];
    const int*   src   = (const int*)d_in[1];
    const int*   dst   = (const int*)d_in[2];
    const float* W1    = (const float*)d_in[3];
    const float* al1   = (const float*)d_in[4];
    const float* ar1   = (const float*)d_in[5];
    const float* b1    = (const float*)d_in[6];
    const float* W2    = (const float*)d_in[7];
    const float* al2   = (const float*)d_in[8];
    const float* ar2   = (const float*)d_in[9];
    const float* b2    = (const float*)d_in[10];
    float* out = (float*)d_out;

    __half* h;
    float* x2;
    unsigned *w1hi, *w1lo, *w2hi, *w2lo, *mxp;
    int *degp;
    cudaGetSymbolAddress((void**)&h, g_h);
    cudaGetSymbolAddress((void**)&x2, g_x2);
    cudaGetSymbolAddress((void**)&w1hi, g_w1hi);
    cudaGetSymbolAddress((void**)&w1lo, g_w1lo);
    cudaGetSymbolAddress((void**)&w2hi, g_w2hi);
    cudaGetSymbolAddress((void**)&w2lo, g_w2lo);
    cudaGetSymbolAddress((void**)&degp, g_deg);
    cudaGetSymbolAddress((void**)&mxp, g_mx);

    // side stream + events (created once; no device allocs)
    static cudaStream_t s2 = nullptr;
    static cudaEvent_t eFork = nullptr, eCsr = nullptr;
    if (s2 == nullptr) {
        cudaStreamCreateWithFlags(&s2, cudaStreamNonBlocking);
        cudaEventCreateWithFlags(&eFork, cudaEventDisableTiming);
        cudaEventCreateWithFlags(&eCsr, cudaEventDisableTiming);
    }

    const int nodeGrid = (N_NODES + 255) / 256;
    const int edgeGrid = (N_EDGES + 255) / 256;
    const int scanBlocks = (N_NODES + 1023) / 1024;
    const int warpGrid = (N_NODES * 32 + 127) / 128;
    const int gemmGrid = (N_NODES + 63) / 64;                 // 64-row tiles
    const int smemGemm = (2 * BUFW + 128 + 8) * 4;            // ~56 KB

    cudaFuncSetAttribute(k_gemm_bf16x3,
                         cudaFuncAttributeMaxDynamicSharedMemorySize, smemGemm);

    // ---- fork: W2 split + CSR build on s2, concurrent with splitW1 + GEMM1 ----
    cudaEventRecord(eFork, 0);
    cudaStreamWaitEvent(s2, eFork, 0);
    k_splitW<<<(128 * HIDDEN / 2 + 255) / 256, 256, 0, s2>>>(W2, w2hi, w2lo,
                                                             128 * HIDDEN / 2);
    cudaMemsetAsync(degp, 0, N_NODES * sizeof(int), s2);
    k_count<<<edgeGrid, 256, 0, s2>>>(dst);
    k_scan1<<<scanBlocks, 1024, 0, s2>>>();
    k_scan2<<<1, 128, 0, s2>>>(scanBlocks);
    k_scan3<<<nodeGrid, 256, 0, s2>>>();
    k_scatter<<<edgeGrid, 256, 0, s2>>>(src, dst);
    cudaEventRecord(eCsr, s2);

    // ---- main stream: weights + layer 1 GEMM ----
    cudaMemsetAsync(mxp, 0, 4 * sizeof(unsigned));
    k_splitW<<<(128 * IN_FEATS / 2 + 255) / 256, 256>>>(W1, w1hi, w1lo, 128 * IN_FEATS / 2);
    k_gemm_bf16x3<<<gemmGrid, 256, smemGemm>>>(feats, w1hi, w1lo, al1, ar1, h,
                                               N_NODES, IN_FEATS, 0);
    cudaStreamWaitEvent(0, eCsr, 0);   // join CSR (and W2 split) before layer-1 agg
    k_agg<<<warpGrid, 128>>>(h, b1, (float4*)x2, 1, 0);

    // ---- layer 2 ----
    k_gemm_bf16x3<<<gemmGrid, 256, smemGemm>>>(x2, w2hi, w2lo, al2, ar2, h,
                                               N_NODES, HIDDEN, 1);
    k_agg<<<warpGrid, 128>>>(h, b2, (float4*)out, 0, 1);
}

// round 16
// speedup vs baseline: 1.0817x; 1.0817x over previous
#include <cuda_runtime.h>
#include <cuda_fp16.h>
#include <math.h>

#define N_NODES 100000
#define N_EDGES 1600000
#define IN_FEATS 256
#define HIDDEN 128
#define NEG_SLOPE 0.2f

// ---------------- scratch (device globals; allocation-free) ----------------
__device__ __half g_h[(size_t)N_NODES * HIDDEN];   // fc output, fp16 (gather-only)
__device__ float g_x2[(size_t)N_NODES * HIDDEN];   // elu(layer1 out) = layer2 input
__device__ float g_el[N_NODES];
__device__ float g_er[N_NODES];
__device__ int   g_deg[N_NODES];
__device__ int   g_inc[N_NODES];
__device__ int   g_bsum[128];
__device__ int   g_off[N_NODES + 1];
__device__ int   g_cur[N_NODES];
__device__ int   g_esrc[N_EDGES];
__device__ unsigned g_mx[4];   // encoded max(el), max(er) per layer
// pre-split weights: packed fp16x2 hi/lo planes
__device__ unsigned g_w1hi[128 * IN_FEATS / 2];
__device__ unsigned g_w1lo[128 * IN_FEATS / 2];
__device__ unsigned g_w2hi[128 * HIDDEN / 2];
__device__ unsigned g_w2lo[128 * HIDDEN / 2];

// ---------------- CSR build ----------------
__global__ void k_count(const int* __restrict__ dst) {
    int i = blockIdx.x * blockDim.x + threadIdx.x;
    if (i < N_EDGES) atomicAdd(&g_deg[dst[i]], 1);
}

__global__ void k_scan1() {
    __shared__ int sm[1024];
    int i = blockIdx.x * 1024 + threadIdx.x;
    int v = (i < N_NODES) ? g_deg[i] : 0;
    sm[threadIdx.x] = v;
    __syncthreads();
    #pragma unroll
    for (int o = 1; o < 1024; o <<= 1) {
        int u = (threadIdx.x >= o) ? sm[threadIdx.x - o] : 0;
        __syncthreads();
        sm[threadIdx.x] += u;
        __syncthreads();
    }
    if (i < N_NODES) g_inc[i] = sm[threadIdx.x];
    if (threadIdx.x == 1023) g_bsum[blockIdx.x] = sm[1023];
}

__global__ void k_scan2(int nb) {
    __shared__ int sm[128];
    int t = threadIdx.x;
    int v = (t < nb) ? g_bsum[t] : 0;
    sm[t] = v;
    __syncthreads();
    #pragma unroll
    for (int o = 1; o < 128; o <<= 1) {
        int u = (t >= o) ? sm[t - o] : 0;
        __syncthreads();
        sm[t] += u;
        __syncthreads();
    }
    if (t < nb) g_bsum[t] = sm[t] - v;  // exclusive
}

__global__ void k_scan3() {
    int i = blockIdx.x * blockDim.x + threadIdx.x;
    if (i < N_NODES) {
        int off = g_inc[i] - g_deg[i] + g_bsum[i >> 10];
        g_off[i] = off;
        g_cur[i] = off;
    }
    if (i == 0) g_off[N_NODES] = N_EDGES;
}

__global__ void k_scatter(const int* __restrict__ src, const int* __restrict__ dst) {
    int i = blockIdx.x * blockDim.x + threadIdx.x;
    if (i < N_EDGES) {
        int p = atomicAdd(&g_cur[dst[i]], 1);
        g_esrc[p] = src[i];
    }
}

// ---------------- one-time weight split: W -> fp16 hi/lo packed planes -----
__global__ void k_splitW16(const float* __restrict__ W, unsigned* __restrict__ hi,
                           unsigned* __restrict__ lo, int npairs) {
    int i = blockIdx.x * blockDim.x + threadIdx.x;
    if (i < npairs) {
        float a = W[2 * i], b = W[2 * i + 1];
        __half ha = __float2half_rn(a), hb = __float2half_rn(b);
        float la = a - __half2float(ha), lb = b - __half2float(hb);
        __half2 h2 = __halves2half2(ha, hb);
        __half2 l2 = __floats2half2_rn(la, lb);
        hi[i] = *(unsigned*)&h2;
        lo[i] = *(unsigned*)&l2;
    }
}

// ---------------- float<->ordered-unsigned for atomicMax ----------------
__device__ __forceinline__ unsigned encf(float f) {
    unsigned u = __float_as_uint(f);
    return (u >> 31) ? ~u : (u | 0x80000000u);
}
__device__ __forceinline__ float decf(unsigned e) {
    return (e >> 31) ? __uint_as_float(e ^ 0x80000000u) : __uint_as_float(~e);
}

// ---------------- fp16x2 tensor-core GEMM + fused el/er + global max ------
// H[M,128] (fp16) = A[M,K] @ W[128,K]^T with A rounded to fp16 once and
// W = Whi + Wlo (fp16 planes): D = A*Whi + A*Wlo, fp32 accum.
// 128x128 tile, 256 threads (8 warps, each 64x32), BK=32, register prefetch,
// double-buffered 3-plane SMEM, single __syncthreads per chunk.

#define SSTR 18                    // uint32 pairs per row: 16 + 2 pad
#define BUFW (3 * 128 * SSTR)      // words per buffer: A, Bhi, Blo

__device__ __forceinline__ void mma16816f(float* d, const unsigned* a, const unsigned* b) {
    asm volatile(
        "mma.sync.aligned.m16n8k16.row.col.f32.f16.f16.f32 "
        "{%0,%1,%2,%3}, {%4,%5,%6,%7}, {%8,%9}, {%0,%1,%2,%3};\n"
        : "+f"(d[0]), "+f"(d[1]), "+f"(d[2]), "+f"(d[3])
        : "r"(a[0]), "r"(a[1]), "r"(a[2]), "r"(a[3]), "r"(b[0]), "r"(b[1]));
}

__global__ __launch_bounds__(256) void k_gemm_fp16x2(
    const float* __restrict__ A,
    const unsigned* __restrict__ Whi, const unsigned* __restrict__ Wlo,
    const float* __restrict__ al, const float* __restrict__ ar,
    __half* __restrict__ H, int M, int K, int layer)
{
    extern __shared__ unsigned dyn[];
    float* sel = (float*)(dyn + 2 * BUFW);   // 128
    float* ser = sel + 128;                   // 128
    float* smax = ser + 128;                  // 8

    const int tid  = threadIdx.x;
    const int lane = tid & 31, wid = tid >> 5;
    const int g = lane >> 2, t = lane & 3;
    const int wm = wid >> 2, wn = wid & 3;    // 2 x 4 warp grid
    const int row0 = blockIdx.x * 128;
    const int K2 = K >> 1;                    // pairs per W row

    if (tid < 128) { sel[tid] = 0.f; ser[tid] = 0.f; }

    float acc[4][4][4];
    #pragma unroll
    for (int mt = 0; mt < 4; mt++)
        #pragma unroll
        for (int nt = 0; nt < 4; nt++)
            #pragma unroll
            for (int j = 0; j < 4; j++) acc[mt][nt][j] = 0.f;

    int lrow[4], lq[4];
    #pragma unroll
    for (int i = 0; i < 4; i++) { int idx = tid + i * 256; lrow[i] = idx >> 3; lq[i] = idx & 7; }

    float4 ra[4];
    uint2 bh[4], bl[4];
    const int NC = K / 32;

    // prologue: load chunk 0 to registers
    #pragma unroll
    for (int i = 0; i < 4; i++) {
        int gr = row0 + lrow[i];
        ra[i] = (gr < M) ? *(const float4*)(A + (size_t)gr * K + lq[i] * 4)
                         : make_float4(0.f, 0.f, 0.f, 0.f);
        int bidx = lrow[i] * K2 + lq[i] * 2;
        bh[i] = *(const uint2*)(Whi + bidx);
        bl[i] = *(const uint2*)(Wlo + bidx);
    }

    for (int c = 0; c < NC; c++) {
        unsigned* sA   = dyn + (c & 1) * BUFW;
        unsigned* sBhi = sA + 128 * SSTR;
        unsigned* sBlo = sBhi + 128 * SSTR;

        // regs -> smem (A converted to fp16; B pre-split)
        #pragma unroll
        for (int i = 0; i < 4; i++) {
            int base = lrow[i] * SSTR + lq[i] * 2;
            __half2 h0 = __floats2half2_rn(ra[i].x, ra[i].y);
            __half2 h1 = __floats2half2_rn(ra[i].z, ra[i].w);
            sA[base] = *(unsigned*)&h0; sA[base + 1] = *(unsigned*)&h1;
            sBhi[base] = bh[i].x; sBhi[base + 1] = bh[i].y;
            sBlo[base] = bl[i].x; sBlo[base + 1] = bl[i].y;
        }
        __syncthreads();   // single barrier per chunk (double-buffered)

        // prefetch next chunk while MMAs run
        if (c + 1 < NC) {
            int k0 = (c + 1) * 32;
            #pragma unroll
            for (int i = 0; i < 4; i++) {
                int gr = row0 + lrow[i];
                ra[i] = (gr < M) ? *(const float4*)(A + (size_t)gr * K + k0 + lq[i] * 4)
                                 : make_float4(0.f, 0.f, 0.f, 0.f);
                int bidx = lrow[i] * K2 + (k0 >> 1) + lq[i] * 2;
                bh[i] = *(const uint2*)(Whi + bidx);
                bl[i] = *(const uint2*)(Wlo + bidx);
            }
        }

        #pragma unroll
        for (int ks = 0; ks < 2; ks++) {
            const int pb = ks * 8;
            unsigned fa[4][4], fbhi[4][2], fblo[4][2];
            #pragma unroll
            for (int mt = 0; mt < 4; mt++) {
                int r0 = (wm * 64 + mt * 16 + g) * SSTR + pb + t;
                int r1 = r0 + 8 * SSTR;
                fa[mt][0] = sA[r0];     fa[mt][1] = sA[r1];
                fa[mt][2] = sA[r0 + 4]; fa[mt][3] = sA[r1 + 4];
            }
            #pragma unroll
            for (int nt = 0; nt < 4; nt++) {
                int rn = (wn * 32 + nt * 8 + g) * SSTR + pb + t;
                fbhi[nt][0] = sBhi[rn]; fbhi[nt][1] = sBhi[rn + 4];
                fblo[nt][0] = sBlo[rn]; fblo[nt][1] = sBlo[rn + 4];
            }
            #pragma unroll
            for (int mt = 0; mt < 4; mt++)
                #pragma unroll
                for (int nt = 0; nt < 4; nt++) {
                    mma16816f(acc[mt][nt], fa[mt], fbhi[nt]);
                    mma16816f(acc[mt][nt], fa[mt], fblo[nt]);
                }
        }
    }
    __syncthreads();

    // epilogue: store H (fp16), and fused el/er row dots (fp32)
    float alv[8], arv[8];
    #pragma unroll
    for (int nt = 0; nt < 4; nt++) {
        int cix = wn * 32 + nt * 8 + t * 2;
        alv[2 * nt] = al[cix];     alv[2 * nt + 1] = al[cix + 1];
        arv[2 * nt] = ar[cix];     arv[2 * nt + 1] = ar[cix + 1];
    }

    #pragma unroll
    for (int mt = 0; mt < 4; mt++) {
        float eA = 0.f, rA = 0.f, eB = 0.f, rB = 0.f;
        #pragma unroll
        for (int nt = 0; nt < 4; nt++) {
            int r = row0 + wm * 64 + mt * 16 + g;
            int col = wn * 32 + nt * 8 + t * 2;
            if (r < M)
                *(__half2*)(H + (size_t)r * 128 + col) =
                    __floats2half2_rn(acc[mt][nt][0], acc[mt][nt][1]);
            if (r + 8 < M)
                *(__half2*)(H + (size_t)(r + 8) * 128 + col) =
                    __floats2half2_rn(acc[mt][nt][2], acc[mt][nt][3]);
            eA += acc[mt][nt][0] * alv[2 * nt] + acc[mt][nt][1] * alv[2 * nt + 1];
            rA += acc[mt][nt][0] * arv[2 * nt] + acc[mt][nt][1] * arv[2 * nt + 1];
            eB += acc[mt][nt][2] * alv[2 * nt] + acc[mt][nt][3] * alv[2 * nt + 1];
            rB += acc[mt][nt][2] * arv[2 * nt] + acc[mt][nt][3] * arv[2 * nt + 1];
        }
        #pragma unroll
        for (int o = 1; o <= 2; o <<= 1) {
            eA += __shfl_xor_sync(0xffffffffu, eA, o);
            rA += __shfl_xor_sync(0xffffffffu, rA, o);
            eB += __shfl_xor_sync(0xffffffffu, eB, o);
            rB += __shfl_xor_sync(0xffffffffu, rB, o);
        }
        if (t == 0) {
            int lr0 = wm * 64 + mt * 16 + g;
            atomicAdd(&sel[lr0], eA);     atomicAdd(&ser[lr0], rA);
            atomicAdd(&sel[lr0 + 8], eB); atomicAdd(&ser[lr0 + 8], rB);
        }
    }
    __syncthreads();

    // write el/er and fold block max into g_mx[2*layer..]
    float mel = -3e38f, mer = -3e38f;
    if (tid < 128) {
        bool valid = (row0 + tid) < M;
        float el = sel[tid], er = ser[tid];
        if (valid) {
            g_el[row0 + tid] = el;
            g_er[row0 + tid] = er;
            mel = el; mer = er;
        }
        #pragma unroll
        for (int o = 16; o; o >>= 1) {
            mel = fmaxf(mel, __shfl_xor_sync(0xffffffffu, mel, o));
            mer = fmaxf(mer, __shfl_xor_sync(0xffffffffu, mer, o));
        }
        if (lane == 0) { smax[wid] = mel; smax[4 + wid] = mer; }
    }
    __syncthreads();
    if (tid == 0) {
        float a = fmaxf(fmaxf(smax[0], smax[1]), fmaxf(smax[2], smax[3]));
        float b = fmaxf(fmaxf(smax[4], smax[5]), fmaxf(smax[6], smax[7]));
        atomicMax(&g_mx[2 * layer], encf(a));
        atomicMax(&g_mx[2 * layer + 1], encf(b));
    }
}

// ---------------- single-pass segment softmax + aggregation (fp16 gathers) ----
__global__ void k_agg(const __half* __restrict__ Hm,
                      const float* __restrict__ bias,
                      float4* __restrict__ out4, int do_elu, int layer)
{
    int warp = (blockIdx.x * blockDim.x + threadIdx.x) >> 5;
    int lane = threadIdx.x & 31;
    if (warp >= N_NODES) return;
    int d = warp;
    int s = g_off[d], e = g_off[d + 1];
    float4 bv = ((const float4*)bias)[lane];
    float4 v;

    if (s == e) {
        v = bv;
    } else {
        float me = decf(g_mx[2 * layer]) + decf(g_mx[2 * layer + 1]);
        float m = (me > 0.f) ? me : NEG_SLOPE * me;
        float er_d = g_er[d];
        float4 acc = make_float4(0.f, 0.f, 0.f, 0.f);
        float sumw = 0.f;
        int i = s;
        for (; i + 3 < e; i += 4) {
            int sn0 = g_esrc[i],     sn1 = g_esrc[i + 1];
            int sn2 = g_esrc[i + 2], sn3 = g_esrc[i + 3];
            float2 r0 = *(const float2*)(Hm + (size_t)sn0 * 128 + lane * 4);
            float2 r1 = *(const float2*)(Hm + (size_t)sn1 * 128 + lane * 4);
            float2 r2 = *(const float2*)(Hm + (size_t)sn2 * 128 + lane * 4);
            float2 r3 = *(const float2*)(Hm + (size_t)sn3 * 128 + lane * 4);
            float x0 = g_el[sn0] + er_d, x1 = g_el[sn1] + er_d;
            float x2v = g_el[sn2] + er_d, x3 = g_el[sn3] + er_d;
            float w0 = __expf(((x0 > 0.f) ? x0 : NEG_SLOPE * x0) - m);
            float w1 = __expf(((x1 > 0.f) ? x1 : NEG_SLOPE * x1) - m);
            float w2 = __expf(((x2v > 0.f) ? x2v : NEG_SLOPE * x2v) - m);
            float w3 = __expf(((x3 > 0.f) ? x3 : NEG_SLOPE * x3) - m);
            sumw += (w0 + w1) + (w2 + w3);
            float2 a0 = __half22float2(*(__half2*)&r0.x), b0 = __half22float2(*(__half2*)&r0.y);
            float2 a1 = __half22float2(*(__half2*)&r1.x), b1 = __half22float2(*(__half2*)&r1.y);
            float2 a2 = __half22float2(*(__half2*)&r2.x), b2 = __half22float2(*(__half2*)&r2.y);
            float2 a3 = __half22float2(*(__half2*)&r3.x), b3 = __half22float2(*(__half2*)&r3.y);
            acc.x += w0 * a0.x + w1 * a1.x + w2 * a2.x + w3 * a3.x;
            acc.y += w0 * a0.y + w1 * a1.y + w2 * a2.y + w3 * a3.y;
            acc.z += w0 * b0.x + w1 * b1.x + w2 * b2.x + w3 * b3.x;
            acc.w += w0 * b0.y + w1 * b1.y + w2 * b2.y + w3 * b3.y;
        }
        for (; i < e; i++) {
            int sn = g_esrc[i];
            float2 r0 = *(const float2*)(Hm + (size_t)sn * 128 + lane * 4);
            float x = g_el[sn] + er_d;
            float w = __expf(((x > 0.f) ? x : NEG_SLOPE * x) - m);
            sumw += w;
            float2 a0 = __half22float2(*(__half2*)&r0.x), b0 = __half22float2(*(__half2*)&r0.y);
            acc.x += w * a0.x; acc.y += w * a0.y;
            acc.z += w * b0.x; acc.w += w * b0.y;
        }
        float inv = 1.f / sumw;
        v = make_float4(acc.x * inv + bv.x, acc.y * inv + bv.y,
                        acc.z * inv + bv.z, acc.w * inv + bv.w);
    }

    if (do_elu) {
        v.x = (v.x > 0.f) ? v.x : (__expf(v.x) - 1.f);
        v.y = (v.y > 0.f) ? v.y : (__expf(v.y) - 1.f);
        v.z = (v.z > 0.f) ? v.z : (__expf(v.z) - 1.f);
        v.w = (v.w > 0.f) ? v.w : (__expf(v.w) - 1.f);
    }
    out4[(size_t)d * 32 + lane] = v;
}

// ---------------- launch ----------------
extern "C" void kernel_launch(void* const* d_in, const int* in_sizes, int n_in,
                              void* d_out, int out_size)
{
    const float* feats = (const float*)d_in[0];
    const int*   src   = (const int*)d_in[1];
    const int*   dst   = (const int*)d_in[2];
    const float* W1    = (const float*)d_in[3];
    const float* al1   = (const float*)d_in[4];
    const float* ar1   = (const float*)d_in[5];
    const float* b1    = (const float*)d_in[6];
    const float* W2    = (const float*)d_in[7];
    const float* al2   = (const float*)d_in[8];
    const float* ar2   = (const float*)d_in[9];
    const float* b2    = (const float*)d_in[10];
    float* out = (float*)d_out;

    __half* h;
    float* x2;
    unsigned *w1hi, *w1lo, *w2hi, *w2lo, *mxp;
    int *degp;
    cudaGetSymbolAddress((void**)&h, g_h);
    cudaGetSymbolAddress((void**)&x2, g_x2);
    cudaGetSymbolAddress((void**)&w1hi, g_w1hi);
    cudaGetSymbolAddress((void**)&w1lo, g_w1lo);
    cudaGetSymbolAddress((void**)&w2hi, g_w2hi);
    cudaGetSymbolAddress((void**)&w2lo, g_w2lo);
    cudaGetSymbolAddress((void**)&degp, g_deg);
    cudaGetSymbolAddress((void**)&mxp, g_mx);

    // side stream + events (created once; no device allocs)
    static cudaStream_t s2 = nullptr;
    static cudaEvent_t eFork = nullptr, eCsr = nullptr;
    if (s2 == nullptr) {
        cudaStreamCreateWithFlags(&s2, cudaStreamNonBlocking);
        cudaEventCreateWithFlags(&eFork, cudaEventDisableTiming);
        cudaEventCreateWithFlags(&eCsr, cudaEventDisableTiming);
    }

    const int nodeGrid = (N_NODES + 255) / 256;
    const int edgeGrid = (N_EDGES + 255) / 256;
    const int scanBlocks = (N_NODES + 1023) / 1024;
    const int warpGrid = (N_NODES * 32 + 127) / 128;
    const int gemmGrid = (N_NODES + 127) / 128;
    const int smemGemm = (2 * BUFW + 256 + 8) * 4;   // ~56.3 KB

    cudaFuncSetAttribute(k_gemm_fp16x2,
                         cudaFuncAttributeMaxDynamicSharedMemorySize, smemGemm);

    // ---- fork: W2 split + CSR build on s2, concurrent with splitW1 + GEMM1 ----
    cudaEventRecord(eFork, 0);
    cudaStreamWaitEvent(s2, eFork, 0);
    k_splitW16<<<(128 * HIDDEN / 2 + 255) / 256, 256, 0, s2>>>(W2, w2hi, w2lo,
                                                               128 * HIDDEN / 2);
    cudaMemsetAsync(degp, 0, N_NODES * sizeof(int), s2);
    k_count<<<edgeGrid, 256, 0, s2>>>(dst);
    k_scan1<<<scanBlocks, 1024, 0, s2>>>();
    k_scan2<<<1, 128, 0, s2>>>(scanBlocks);
    k_scan3<<<nodeGrid, 256, 0, s2>>>();
    k_scatter<<<edgeGrid, 256, 0, s2>>>(src, dst);
    cudaEventRecord(eCsr, s2);

    // ---- main stream: weights + layer 1 GEMM ----
    cudaMemsetAsync(mxp, 0, 4 * sizeof(unsigned));
    k_splitW16<<<(128 * IN_FEATS / 2 + 255) / 256, 256>>>(W1, w1hi, w1lo,
                                                          128 * IN_FEATS / 2);
    k_gemm_fp16x2<<<gemmGrid, 256, smemGemm>>>(feats, w1hi, w1lo, al1, ar1, h,
                                               N_NODES, IN_FEATS, 0);
    cudaStreamWaitEvent(0, eCsr, 0);   // join CSR (and W2 split) before layer-1 agg
    k_agg<<<warpGrid, 128>>>(h, b1, (float4*)x2, 1, 0);

    // ---- layer 2 ----
    k_gemm_fp16x2<<<gemmGrid, 256, smemGemm>>>(x2, w2hi, w2lo, al2, ar2, h,
                                               N_NODES, HIDDEN, 1);
    k_agg<<<warpGrid, 128>>>(h, b2, (float4*)out, 0, 1);
}